// round 11
// baseline (speedup 1.0000x reference)
#include <cuda_runtime.h>

// Problem constants
#define Bc     32
#define Ic     1152
#define Oc     10
#define Dc     16
#define Hc     10
#define Sc     922
#define HALF_I 576
#define ROW    20          // padded row stride (floats), 16B-aligned
#define NPAIR  (Bc * Oc)   // 320
#define NCHUNK 9           // K2: 9 chunks x 128 rows
#define K1_THR 256
#define K2_THR 256

// Inter-kernel scratch
// g_part[pair][half][slot][17]: slot0 = T/N of half; slot 1+h = C_h/c_h of half
__device__ float g_part[NPAIR][2][11][17];
// g_loss[pair][chunk][h]
__device__ float g_loss[NPAIR][NCHUNK][Hc];
// completion counters (zero-init; reset by last CTA each replay)
__device__ int   g_sem[NPAIR];

// K1 dynamic smem: u_s 576*20 f | vnS 576 f | red 8*17 f | det 1 | bm 180 u32
#define K1_SMEM ((HALF_I*ROW + HALF_I + 8*17 + 1 + 180) * 4)

__device__ __forceinline__ float sqrt_approx(float x) {
    float r; asm("sqrt.approx.f32 %0, %1;" : "=f"(r) : "f"(x)); return r;
}

__device__ __forceinline__ void load_row_s(const float* __restrict__ rp, float f[16]) {
    float4 a = *(const float4*)(rp + 0);
    float4 b = *(const float4*)(rp + 4);
    float4 c = *(const float4*)(rp + 8);
    float4 d = *(const float4*)(rp + 12);
    f[0]=a.x; f[1]=a.y; f[2]=a.z;  f[3]=a.w;
    f[4]=b.x; f[5]=b.y; f[6]=b.z;  f[7]=b.w;
    f[8]=c.x; f[9]=c.y; f[10]=c.z; f[11]=c.w;
    f[12]=d.x; f[13]=d.y; f[14]=d.z; f[15]=d.w;
}

// ========== K1: sidx scan + staged T/N + complement (per pair-half) ========
extern "C" __global__ void __launch_bounds__(K1_THR, 4)
k1_partials(const float* __restrict__ u, const unsigned int* __restrict__ sidx_raw)
{
    extern __shared__ float sm[];
    float*    u_s = sm;                       // [HALF_I][ROW]
    float*    vnS = u_s + HALF_I * ROW;       // [HALF_I]
    float*    red = vnS + HALF_I;             // [8][17]
    int*      det = (int*)(red + 8 * 17);
    unsigned* bm  = (unsigned*)(det + 1);     // [Hc][18] sampled-mask words, THIS half

    const int o    = blockIdx.x;
    const int b    = blockIdx.y;
    const int half = blockIdx.z;
    const int pair = b * Oc + o;
    const int i0   = half * HALF_I;
    const int tid  = threadIdx.x;
    const int w    = tid >> 5;
    const int lane = tid & 31;

    if (tid < Hc * 18) bm[tid] = 0u;          // 180 < 256: one shot
    // dtype detect: int64 <=> odd 32-bit words of first 128 elems all zero
    if (w == 0) {
        unsigned a = 0;
        #pragma unroll
        for (int j = 0; j < 4; j++) a |= __ldg(sidx_raw + 2 * (lane * 4 + j) + 1);
        unsigned bal = __ballot_sync(0xffffffffu, a != 0);
        if (lane == 0) *det = (bal == 0) ? 1 : 0;
    }
    __syncthreads();
    const bool is64 = (*det != 0);

    // ---- stage this half's u rows (coalesced float4; 9*256 = 2304 exact) --
    {
        const float4* gp = (const float4*)u + ((size_t)((size_t)b * Ic + i0) * Oc + o) * 4;
        #pragma unroll
        for (int k = 0; k < 9; k++) {
            int t = tid + k * K1_THR;
            int i = t >> 2, q = t & 3;
            float4 v = __ldg(gp + (size_t)i * (Oc * 4) + q);
            *(float4*)&u_s[i * ROW + q * 4] = v;
        }
    }

    // ---- sidx scan (full stream; mark only this half's bits) ---------------
    // EXTENT: 37 * 256 = 9472 >= Sc*Hc = 9220
    {
        const size_t sbase = (((size_t)b * Sc) * Oc + o) * Hc;
        #pragma unroll 4
        for (int k = 0; k < 37; k++) {
            int t = tid + k * K1_THR;
            if (t < Sc * Hc) {
                int s = (int)(((unsigned)t * 52429u) >> 19);   // t/10 for t<81920
                int h = t - s * 10;
                size_t off = sbase + (size_t)s * 100 + h;
                unsigned v = is64 ? __ldg(sidx_raw + off * 2) : __ldg(sidx_raw + off);
                unsigned loc = v - (unsigned)i0;
                if (loc < HALF_I)
                    atomicOr(&bm[h * 18 + (loc >> 5)], 1u << (loc & 31));
            }
        }
    }
    __syncthreads();

    // ---- norms + T/N partials over this half (3*256 >= 576) ---------------
    {
        float tA[17];
        #pragma unroll
        for (int j = 0; j < 17; j++) tA[j] = 0.f;
        #pragma unroll
        for (int k = 0; k < 3; k++) {
            int i = tid + k * K1_THR;
            if (i < HALF_I) {
                float f[16];
                load_row_s(&u_s[i * ROW], f);
                float ss = 0.f;
                #pragma unroll
                for (int d = 0; d < Dc; d++) ss = fmaf(f[d], f[d], ss);
                float vn = sqrt_approx(ss);
                vnS[i] = vn;
                tA[16] += vn;
                #pragma unroll
                for (int d = 0; d < Dc; d++) tA[d] = fmaf(vn, f[d], tA[d]);
            }
        }
        #pragma unroll
        for (int off = 16; off; off >>= 1)
            #pragma unroll
            for (int j = 0; j < 17; j++)
                tA[j] += __shfl_down_sync(0xffffffffu, tA[j], off);
        if (lane == 0) {
            #pragma unroll
            for (int j = 0; j < 17; j++) red[w * 17 + j] = tA[j];
        }
    }
    __syncthreads();

    if (tid < 17) {
        float s = 0.f;
        #pragma unroll
        for (int ww = 0; ww < 8; ww++) s += red[ww * 17 + tid];
        g_part[pair][half][0][tid] = s;
    }

    // ---- complement gather from smem: warp w -> h = w; w<2 also h = w+8 ----
    #pragma unroll
    for (int rep = 0; rep < 2; rep++) {
        int hh = w + rep * 8;
        if (hh < Hc) {
            float cA[17];
            #pragma unroll
            for (int q = 0; q < 17; q++) cA[q] = 0.f;

            #pragma unroll 3
            for (int wd = 0; wd < 18; wd++) {
                unsigned bits = bm[hh * 18 + wd];     // broadcast LDS
                if (!((bits >> lane) & 1u)) {         // complement bit
                    int i = wd * 32 + lane;           // local row in [0,576)
                    float f[16];
                    load_row_s(&u_s[i * ROW], f);
                    float vn = vnS[i];                // identical to T-pass value
                    cA[16] += vn;
                    #pragma unroll
                    for (int d = 0; d < Dc; d++) cA[d] = fmaf(vn, f[d], cA[d]);
                }
            }
            #pragma unroll
            for (int off = 16; off; off >>= 1)
                #pragma unroll
                for (int q = 0; q < 17; q++)
                    cA[q] += __shfl_down_sync(0xffffffffu, cA[q], off);
            if (lane == 0) {
                #pragma unroll
                for (int q = 0; q < 17; q++) g_part[pair][half][1 + hh][q] = cA[q];
            }
        }
    }
}

// ===== K2: staged per-chunk losses + last-CTA argmin/emit ==================
extern "C" __global__ void __launch_bounds__(K2_THR, 4)
k2_loss(const float* __restrict__ u, float* __restrict__ out)
{
    __shared__ float u_c[128 * ROW];
    __shared__ float mu[Hc * Dc];
    __shared__ float mm[Hc];
    __shared__ float red[8 * 5];
    __shared__ int   lastflag;

    const int o    = blockIdx.x;
    const int b    = blockIdx.y;
    const int ch   = blockIdx.z;
    const int pair = b * Oc + o;
    const int tid  = threadIdx.x;
    const int w    = tid >> 5;
    const int lane = tid & 31;
    const int r    = tid & 127;
    const int g    = tid >> 7;        // 0 -> h 0..4, 1 -> h 5..9

    // Mu[h][d] = (T - C_h) / (N - c_h)  (same fixed-order value in every CTA)
    if (tid < Hc * Dc) {
        int h = tid >> 4, d = tid & 15;
        float T = g_part[pair][0][0][d]      + g_part[pair][1][0][d];
        float N = g_part[pair][0][0][16]     + g_part[pair][1][0][16];
        float C = g_part[pair][0][1 + h][d]  + g_part[pair][1][1 + h][d];
        float c = g_part[pair][0][1 + h][16] + g_part[pair][1][1 + h][16];
        mu[tid] = (T - C) / (N - c);
    }
    // stage this 128-row chunk (coalesced; 2*256 = 512 = 128*4 exact)
    {
        const float4* gp = (const float4*)u + ((size_t)b * Ic * Oc + o) * 4;
        #pragma unroll
        for (int k = 0; k < 2; k++) {
            int t = tid + k * K2_THR;
            int i = t >> 2, q = t & 3;
            float4 v = __ldg(gp + (size_t)(ch * 128 + i) * (Oc * 4) + q);
            *(float4*)&u_c[i * ROW + q * 4] = v;
        }
    }
    __syncthreads();
    if (tid < Hc) {
        float s = 0.f;
        #pragma unroll
        for (int d = 0; d < Dc; d++) s = fmaf(mu[tid * 16 + d], mu[tid * 16 + d], s);
        mm[tid] = s;
    }
    __syncthreads();

    // losses: ||u - mu||^2 = ||u||^2 - 2 u.mu + ||mu||^2
    float pl[5] = {0.f, 0.f, 0.f, 0.f, 0.f};
    {
        float f[16];
        load_row_s(&u_c[r * ROW], f);
        float ss = 0.f;
        #pragma unroll
        for (int d = 0; d < Dc; d++) ss = fmaf(f[d], f[d], ss);

        #pragma unroll
        for (int j = 0; j < 5; j++) {
            int h = g * 5 + j;
            const float4* mp = (const float4*)&mu[h * 16];   // broadcast LDS.128
            float4 m0 = mp[0], m1 = mp[1], m2 = mp[2], m3 = mp[3];
            float dot = 0.f;
            dot = fmaf(f[0],  m0.x, dot); dot = fmaf(f[1],  m0.y, dot);
            dot = fmaf(f[2],  m0.z, dot); dot = fmaf(f[3],  m0.w, dot);
            dot = fmaf(f[4],  m1.x, dot); dot = fmaf(f[5],  m1.y, dot);
            dot = fmaf(f[6],  m1.z, dot); dot = fmaf(f[7],  m1.w, dot);
            dot = fmaf(f[8],  m2.x, dot); dot = fmaf(f[9],  m2.y, dot);
            dot = fmaf(f[10], m2.z, dot); dot = fmaf(f[11], m2.w, dot);
            dot = fmaf(f[12], m3.x, dot); dot = fmaf(f[13], m3.y, dot);
            dot = fmaf(f[14], m3.z, dot); dot = fmaf(f[15], m3.w, dot);
            float val = fmaf(-2.f, dot, ss + mm[h]);
            pl[j] += sqrt_approx(fmaxf(val, 0.f));
        }
    }
    #pragma unroll
    for (int off = 16; off; off >>= 1)
        #pragma unroll
        for (int j = 0; j < 5; j++)
            pl[j] += __shfl_down_sync(0xffffffffu, pl[j], off);
    if (lane == 0) {
        #pragma unroll
        for (int j = 0; j < 5; j++) red[w * 5 + j] = pl[j];
    }
    __syncthreads();

    if (tid < Hc) {
        int g2 = tid / 5, j = tid - g2 * 5;
        float s = 0.f;
        #pragma unroll
        for (int ww = 0; ww < 4; ww++) s += red[(g2 * 4 + ww) * 5 + j];
        g_loss[pair][ch][tid] = s;
    }
    __syncthreads();

    // ---- last-CTA-done: fold final reduction + emit into this launch ------
    if (tid == 0) {
        __threadfence();                         // release our g_loss chunk
        int old = atomicAdd(&g_sem[pair], 1);
        lastflag = (old == NCHUNK - 1);
        if (lastflag) __threadfence();           // acquire all chunks
    }
    __syncthreads();

    if (lastflag) {
        if (tid == 0) g_sem[pair] = 0;           // reset for next graph replay
        if (w == 0) {
            float L = 3.0e38f;
            if (lane < Hc) {
                float s = 0.f;
                #pragma unroll
                for (int c = 0; c < NCHUNK; c++) s += g_loss[pair][c][lane];
                L = s;
            }
            // first-occurrence argmin across h (all lanes same result)
            int hm = 0;
            float best = __shfl_sync(0xffffffffu, L, 0);
            #pragma unroll
            for (int h = 1; h < Hc; h++) {
                float v = __shfl_sync(0xffffffffu, L, h);
                if (v < best) { best = v; hm = h; }
            }
            if (lane < Dc)
                out[(size_t)pair * Dc + lane] = mu[hm * Dc + lane];
        }
    }
}

extern "C" void kernel_launch(void* const* d_in, const int* in_sizes, int n_in,
                              void* d_out, int out_size)
{
    const float*        u    = (const float*)d_in[0];
    const unsigned int* sidx = (const unsigned int*)d_in[1];
    float*              out  = (float*)d_out;

    cudaFuncSetAttribute(k1_partials,
                         cudaFuncAttributeMaxDynamicSharedMemorySize, K1_SMEM);

    k1_partials<<<dim3(Oc, Bc, 2), K1_THR, K1_SMEM>>>(u, sidx);
    k2_loss<<<dim3(Oc, Bc, NCHUNK), K2_THR>>>(u, out);
}